// round 2
// baseline (speedup 1.0000x reference)
#include <cuda_runtime.h>
#include <cuda_bf16.h>

// out[s,b,d] = x[s,b,0]*W_xy[d,0] + x[s,b,1]*W_xy[d,1]
//            + x[s,b,2]*W_seg[d] + b_xy[d] + b_seg[d] + pe[s,d]
//
// S=256, B=256, D=1024, fp32 out = 268 MB -> pure store-bandwidth bound.
//
// R2: single-wave balanced-run kernel.
//  - grid = 152 SM * 8 CTA = 1216 (exactly one wave, no wave-transition idle)
//  - tiles of 8 b-rows; 8192 tiles split into contiguous runs of 6-7 per block
//  - per-d coefficients live in registers for the whole block; pe[s] reloaded
//    only when s changes (runs are contiguous -> at most 2 s values per block)
//  - x broadcast via uniform __ldg (no smem, no __syncthreads)
//  - streaming stores (__stcs): output is never re-read

#define S_DIM 256
#define B_DIM 256
#define D_DIM 1024
#define B_PER 8
#define CHUNKS (B_DIM / B_PER)          // 32 chunks per s
#define TILES  (S_DIM * CHUNKS)         // 8192
#define NSM    152
#define OCC    8
#define GRID_N (NSM * OCC)              // 1216

__global__ __launch_bounds__(256, OCC)
void pe_fused_kernel(const float* __restrict__ x,
                     const float* __restrict__ Wxy,
                     const float* __restrict__ bxy,
                     const float* __restrict__ Wseg,
                     const float* __restrict__ bseg,
                     const float* __restrict__ pe,
                     float* __restrict__ out)
{
    const int d = threadIdx.x << 2;     // this thread's float4 slice of D

    // Block-lifetime coefficients (s-invariant).
    const float4 w01 = *reinterpret_cast<const float4*>(Wxy + d * 2);
    const float4 w23 = *reinterpret_cast<const float4*>(Wxy + d * 2 + 4);
    const float4 c2  = *reinterpret_cast<const float4*>(Wseg + d);
    const float4 ba  = *reinterpret_cast<const float4*>(bxy + d);
    const float4 bs  = *reinterpret_cast<const float4*>(bseg + d);

    const float c0x = w01.x, c1x = w01.y;   // d+0
    const float c0y = w01.z, c1y = w01.w;   // d+1
    const float c0z = w23.x, c1z = w23.y;   // d+2
    const float c0w = w23.z, c1w = w23.w;   // d+3

    float4 bsum;                        // b_xy + b_seg (s-invariant part of base)
    bsum.x = ba.x + bs.x;
    bsum.y = ba.y + bs.y;
    bsum.z = ba.z + bs.z;
    bsum.w = ba.w + bs.w;

    // Balanced contiguous run assignment: first REM blocks get BASE+1 tiles.
    const int k     = blockIdx.x;
    const int BASE  = TILES / GRID_N;                  // 6
    const int REM   = TILES - BASE * GRID_N;           // 896
    const int extra = (k < REM) ? k : REM;
    const int start = k * BASE + extra;
    const int count = BASE + (k < REM ? 1 : 0);

    int   cur_s = -1;
    float4 base = bsum;                 // will be overwritten on first s

    for (int t = start; t < start + count; ++t) {
        const int s  = t >> 5;          // / CHUNKS
        const int b0 = (t & (CHUNKS - 1)) * B_PER;

        if (s != cur_s) {
            const float4 p = *reinterpret_cast<const float4*>(
                pe + (size_t)s * D_DIM + d);
            base.x = p.x + bsum.x;
            base.y = p.y + bsum.y;
            base.z = p.z + bsum.z;
            base.w = p.w + bsum.w;
            cur_s = s;
        }

        const float* xr = x + (size_t)(s * B_DIM + b0) * 3;
        float* o = out + (size_t)(s * B_DIM + b0) * D_DIM + d;

        #pragma unroll
        for (int i = 0; i < B_PER; ++i) {
            const float x0 = __ldg(xr + i * 3 + 0);   // uniform broadcast loads
            const float x1 = __ldg(xr + i * 3 + 1);
            const float x2 = __ldg(xr + i * 3 + 2);
            float4 r;
            r.x = fmaf(x0, c0x, fmaf(x1, c1x, fmaf(x2, c2.x, base.x)));
            r.y = fmaf(x0, c0y, fmaf(x1, c1y, fmaf(x2, c2.y, base.y)));
            r.z = fmaf(x0, c0z, fmaf(x1, c1z, fmaf(x2, c2.z, base.z)));
            r.w = fmaf(x0, c0w, fmaf(x1, c1w, fmaf(x2, c2.w, base.w)));
            __stcs(reinterpret_cast<float4*>(o + i * D_DIM), r);
        }
    }
}

extern "C" void kernel_launch(void* const* d_in, const int* in_sizes, int n_in,
                              void* d_out, int out_size)
{
    const float* x    = (const float*)d_in[0];   // [S,B,3]
    const float* Wxy  = (const float*)d_in[1];   // [D,2]
    const float* bxy  = (const float*)d_in[2];   // [D]
    const float* Wseg = (const float*)d_in[3];   // [D,1]
    const float* bseg = (const float*)d_in[4];   // [D]
    const float* pe   = (const float*)d_in[5];   // [MAX_LEN,1,D]
    float* out = (float*)d_out;                  // [S,B,D]

    pe_fused_kernel<<<GRID_N, 256>>>(x, Wxy, bxy, Wseg, bseg, pe, out);
}

// round 3
// speedup vs baseline: 1.0114x; 1.0114x over previous
#include <cuda_runtime.h>
#include <cuda_bf16.h>

// out[s,b,d] = x[s,b,0]*W_xy[d,0] + x[s,b,1]*W_xy[d,1]
//            + x[s,b,2]*W_seg[d] + b_xy[d] + b_seg[d] + pe[s,d]
//
// S=256, B=256, D=1024 fp32 -> 268 MB output, pure store-bandwidth bound.
//
// R3: persistent one-wave kernel.
//  - grid = 152 SM x 8 CTA = 1216, exactly one wave (zero wave-tail idle)
//  - each block owns a contiguous run of 53-54 (s,b) rows; stages all its
//    x values into smem ONCE (one __syncthreads per block lifetime)
//  - steady state per row: 3 broadcast LDS + 12 FFMA + 1 STG.128 (streaming)
//  - coefficients in registers for block lifetime; pe reloaded at most once
//    (a 54-row contiguous run crosses at most one s boundary)

#define S_DIM 256
#define B_DIM 256
#define D_DIM 1024
#define NSM    152
#define OCC    8
#define GRID_N (NSM * OCC)                  // 1216
#define ROWS   (S_DIM * B_DIM)              // 65536
#define BASE_R (ROWS / GRID_N)              // 53
#define REM_R  (ROWS - BASE_R * GRID_N)     // 1088
#define MAX_RUN (BASE_R + 1)                // 54

__global__ __launch_bounds__(256, OCC)
void pe_fused_kernel(const float* __restrict__ x,
                     const float* __restrict__ Wxy,
                     const float* __restrict__ bxy,
                     const float* __restrict__ Wseg,
                     const float* __restrict__ bseg,
                     const float* __restrict__ pe,
                     float* __restrict__ out)
{
    __shared__ float xs[MAX_RUN * 3 + 2];   // up to 162 floats

    const int k = blockIdx.x;
    const int extra = (k < REM_R) ? k : REM_R;
    const int start = k * BASE_R + extra;               // first row (s*B+b)
    const int count = BASE_R + (k < REM_R ? 1 : 0);     // 53 or 54

    // Stage x[start : start+count, 0:3] into shared (contiguous floats).
    const int nflt = count * 3;
    if (threadIdx.x < nflt)
        xs[threadIdx.x] = x[(size_t)start * 3 + threadIdx.x];

    const int d = threadIdx.x << 2;         // this thread's float4 slice of D

    // Block-lifetime per-d coefficients.
    const float4 w01 = *reinterpret_cast<const float4*>(Wxy + d * 2);
    const float4 w23 = *reinterpret_cast<const float4*>(Wxy + d * 2 + 4);
    const float4 c2  = *reinterpret_cast<const float4*>(Wseg + d);
    const float4 ba  = *reinterpret_cast<const float4*>(bxy + d);
    const float4 bs  = *reinterpret_cast<const float4*>(bseg + d);

    const float c0x = w01.x, c1x = w01.y;   // d+0
    const float c0y = w01.z, c1y = w01.w;   // d+1
    const float c0z = w23.x, c1z = w23.y;   // d+2
    const float c0w = w23.z, c1w = w23.w;   // d+3

    float4 bsum;                            // b_xy + b_seg
    bsum.x = ba.x + bs.x;
    bsum.y = ba.y + bs.y;
    bsum.z = ba.z + bs.z;
    bsum.w = ba.w + bs.w;

    __syncthreads();

    // Run crosses at most one s boundary (count <= 54 < 256).
    int r = start;
    int remaining = count;
    while (remaining > 0) {
        const int s = r >> 8;                           // / B_DIM
        int rows_s = ((s + 1) << 8) - r;                // rows left in this s
        if (rows_s > remaining) rows_s = remaining;

        const float4 p = *reinterpret_cast<const float4*>(
            pe + (size_t)s * D_DIM + d);
        float4 base;
        base.x = p.x + bsum.x;
        base.y = p.y + bsum.y;
        base.z = p.z + bsum.z;
        base.w = p.w + bsum.w;

        float* o = out + (size_t)r * D_DIM + d;
        const float* xi = xs + (r - start) * 3;

        #pragma unroll 4
        for (int i = 0; i < rows_s; ++i) {
            const float x0 = xi[i * 3 + 0];
            const float x1 = xi[i * 3 + 1];
            const float x2 = xi[i * 3 + 2];
            float4 v;
            v.x = fmaf(x0, c0x, fmaf(x1, c1x, fmaf(x2, c2.x, base.x)));
            v.y = fmaf(x0, c0y, fmaf(x1, c1y, fmaf(x2, c2.y, base.y)));
            v.z = fmaf(x0, c0z, fmaf(x1, c1z, fmaf(x2, c2.z, base.z)));
            v.w = fmaf(x0, c0w, fmaf(x1, c1w, fmaf(x2, c2.w, base.w)));
            __stcs(reinterpret_cast<float4*>(o + (size_t)i * D_DIM), v);
        }

        r += rows_s;
        remaining -= rows_s;
    }
}

extern "C" void kernel_launch(void* const* d_in, const int* in_sizes, int n_in,
                              void* d_out, int out_size)
{
    const float* x    = (const float*)d_in[0];   // [S,B,3]
    const float* Wxy  = (const float*)d_in[1];   // [D,2]
    const float* bxy  = (const float*)d_in[2];   // [D]
    const float* Wseg = (const float*)d_in[3];   // [D,1]
    const float* bseg = (const float*)d_in[4];   // [D]
    const float* pe   = (const float*)d_in[5];   // [MAX_LEN,1,D]
    float* out = (float*)d_out;                  // [S,B,D]

    pe_fused_kernel<<<GRID_N, 256>>>(x, Wxy, bxy, Wseg, bseg, pe, out);
}